// round 4
// baseline (speedup 1.0000x reference)
#include <cuda_runtime.h>
#include <math_constants.h>

// Problem constants: B=16, N=1024, M=512, D=512
#define B_ 16
#define N_ 1024
#define M_ 512
#define D_ 512

// Scratch (device globals; no allocation allowed)
__device__ float g_sim[B_ * N_ * M_];   // similarity, then S1 in-place (32 MB)
__device__ float g_S2 [B_ * N_ * M_];   // S2 (32 MB)
__device__ float g_Bt [B_ * N_ * N_];   // S1 @ S2^T (64 MB)
__device__ float g_cw [B_ * N_];        // C @ w4C
__device__ float g_qw [B_ * M_];        // Q @ w4Q

// ---------------------------------------------------------------------------
// Row-dot: out[row] = sum_d X[row,d] * w[d], D_=512, one warp per row
// ---------------------------------------------------------------------------
__global__ __launch_bounds__(256)
void rowdot_kernel(const float* __restrict__ X, const float* __restrict__ w,
                   float* __restrict__ out, int rows)
{
    int warp = (blockIdx.x * blockDim.x + threadIdx.x) >> 5;
    int lane = threadIdx.x & 31;
    if (warp >= rows) return;
    const float4* x4 = (const float4*)(X + (long)warp * D_);
    const float4* w4 = (const float4*)w;
    float s = 0.f;
    #pragma unroll
    for (int i = 0; i < 4; ++i) {
        float4 a = x4[lane + 32 * i];
        float4 b = w4[lane + 32 * i];
        s += a.x * b.x + a.y * b.y + a.z * b.z + a.w * b.w;
    }
    #pragma unroll
    for (int o = 16; o; o >>= 1) s += __shfl_xor_sync(0xffffffffu, s, o);
    if (lane == 0) out[warp] = s;
}

// ---------------------------------------------------------------------------
// Dual softmax over M=512 per row of g_sim.
//   S1: mask Qmask over columns, write back into g_sim
//   S2: mask Cmask per-row scalar (row masked -> NaN, matches reference), g_S2
// One block of 128 threads per row, float4 per thread.
// ---------------------------------------------------------------------------
__global__ __launch_bounds__(128)
void softmax2_kernel(const float* __restrict__ Qmask, const float* __restrict__ Cmask)
{
    int row = blockIdx.x;            // b*N + n
    int b   = row >> 10;             // N_=1024
    int t   = threadIdx.x;
    int w   = t >> 5, lane = t & 31;

    float4 v  = ((const float4*)(g_sim + (long)row * M_))[t];
    float4 qm = ((const float4*)(Qmask + (long)b * M_))[t];
    float xv[4] = {v.x, v.y, v.z, v.w};
    float qv[4] = {qm.x, qm.y, qm.z, qm.w};

    float m1 = -CUDART_INF_F, m2 = -CUDART_INF_F;
    #pragma unroll
    for (int j = 0; j < 4; ++j) {
        m2 = fmaxf(m2, xv[j]);
        if (qv[j] != 0.f) m1 = fmaxf(m1, xv[j]);
    }
    #pragma unroll
    for (int o = 16; o; o >>= 1) {
        m1 = fmaxf(m1, __shfl_xor_sync(0xffffffffu, m1, o));
        m2 = fmaxf(m2, __shfl_xor_sync(0xffffffffu, m2, o));
    }
    __shared__ float sh1[4], sh2[4];
    if (lane == 0) { sh1[w] = m1; sh2[w] = m2; }
    __syncthreads();
    m1 = fmaxf(fmaxf(sh1[0], sh1[1]), fmaxf(sh1[2], sh1[3]));
    m2 = fmaxf(fmaxf(sh2[0], sh2[1]), fmaxf(sh2[2], sh2[3]));

    float e1[4], e2[4], s1 = 0.f, s2 = 0.f;
    #pragma unroll
    for (int j = 0; j < 4; ++j) {
        e2[j] = __expf(xv[j] - m2);              s2 += e2[j];
        e1[j] = (qv[j] != 0.f) ? __expf(xv[j] - m1) : 0.f;  s1 += e1[j];
    }
    #pragma unroll
    for (int o = 16; o; o >>= 1) {
        s1 += __shfl_xor_sync(0xffffffffu, s1, o);
        s2 += __shfl_xor_sync(0xffffffffu, s2, o);
    }
    __syncthreads();
    if (lane == 0) { sh1[w] = s1; sh2[w] = s2; }
    __syncthreads();
    s1 = sh1[0] + sh1[1] + sh1[2] + sh1[3];
    s2 = sh2[0] + sh2[1] + sh2[2] + sh2[3];

    float r1 = 1.f / s1;
    float cm = Cmask[row];
    float r2 = (cm != 0.f) ? (1.f / s2) : __int_as_float(0x7FC00000);

    ((float4*)(g_sim + (long)row * M_))[t] =
        make_float4(e1[0] * r1, e1[1] * r1, e1[2] * r1, e1[3] * r1);
    ((float4*)(g_S2 + (long)row * M_))[t] =
        make_float4(e2[0] * r2, e2[1] * r2, e2[2] * r2, e2[3] * r2);
}

// ---------------------------------------------------------------------------
// Register-blocked SGEMM: 128x128 tile, BK=16, 256 threads, 8x8 per thread.
// A row-major [rows,K] (lda). B: if BT, B[col,k] (ldb=K-ish); else B[k,col].
// EPI: 0 = similarity (+cw+qw+bias -> Og)
//      1 = plain store -> Og
//      2 = A-epilogue: out[.,0:512]=C, out[.,512:1024]=acc, out[.,1024:1536]=C*acc
//      3 = Bv-epilogue: out[.,1536:2048]=C*acc
// All dims are multiples of the tile sizes for this problem.
// ---------------------------------------------------------------------------
template<int EPI, bool BT, bool SCALEA>
__global__ __launch_bounds__(256, 2)
void sgemm_kernel(const float* __restrict__ Ag, long sAb, int lda,
                  const float* __restrict__ Bg, long sBb, int ldb,
                  float* __restrict__ Og, long sOb, int ldo,
                  int K,
                  const float* __restrict__ wscale,
                  const float* __restrict__ cw,
                  const float* __restrict__ qw,
                  const float* __restrict__ biasp,
                  const float* __restrict__ Cin)
{
    const int b       = blockIdx.z;
    const int rowBase = blockIdx.y * 128;
    const int colBase = blockIdx.x * 128;
    const float* A  = Ag + (long)b * sAb;
    const float* Bp = Bg + (long)b * sBb;

    __shared__ float As[16][132];
    __shared__ float Bs[16][132];

    const int tid = threadIdx.x;
    const int tx  = tid & 15;
    const int ty  = tid >> 4;

    float acc[8][8];
    #pragma unroll
    for (int i = 0; i < 8; ++i)
        #pragma unroll
        for (int j = 0; j < 8; ++j) acc[i][j] = 0.f;

    for (int k0 = 0; k0 < K; k0 += 16) {
        // ---- load A tile (128 rows x 16 k), store transposed As[k][row]
        #pragma unroll
        for (int it = 0; it < 2; ++it) {
            int v  = tid + it * 256;
            int r  = v >> 2;
            int kq = (v & 3) << 2;
            float4 a = *(const float4*)(A + (long)(rowBase + r) * lda + k0 + kq);
            if (SCALEA) {
                a.x *= wscale[k0 + kq + 0]; a.y *= wscale[k0 + kq + 1];
                a.z *= wscale[k0 + kq + 2]; a.w *= wscale[k0 + kq + 3];
            }
            As[kq + 0][r] = a.x; As[kq + 1][r] = a.y;
            As[kq + 2][r] = a.z; As[kq + 3][r] = a.w;
        }
        // ---- load B tile -> Bs[k][col]
        if (BT) {
            #pragma unroll
            for (int it = 0; it < 2; ++it) {
                int v  = tid + it * 256;
                int c  = v >> 2;
                int kq = (v & 3) << 2;
                float4 bb = *(const float4*)(Bp + (long)(colBase + c) * ldb + k0 + kq);
                Bs[kq + 0][c] = bb.x; Bs[kq + 1][c] = bb.y;
                Bs[kq + 2][c] = bb.z; Bs[kq + 3][c] = bb.w;
            }
        } else {
            #pragma unroll
            for (int it = 0; it < 2; ++it) {
                int v  = tid + it * 256;
                int k  = v >> 5;
                int c4 = (v & 31) << 2;
                float4 bb = *(const float4*)(Bp + (long)(k0 + k) * ldb + colBase + c4);
                *(float4*)&Bs[k][c4] = bb;
            }
        }
        __syncthreads();

        #pragma unroll
        for (int k = 0; k < 16; ++k) {
            float ar[8], br[8];
            *(float4*)(ar)     = *(const float4*)&As[k][ty * 8];
            *(float4*)(ar + 4) = *(const float4*)&As[k][ty * 8 + 4];
            *(float4*)(br)     = *(const float4*)&Bs[k][tx * 8];
            *(float4*)(br + 4) = *(const float4*)&Bs[k][tx * 8 + 4];
            #pragma unroll
            for (int i = 0; i < 8; ++i)
                #pragma unroll
                for (int j = 0; j < 8; ++j)
                    acc[i][j] = fmaf(ar[i], br[j], acc[i][j]);
        }
        __syncthreads();
    }

    const int gr = rowBase + ty * 8;
    const int gc = colBase + tx * 8;

    if (EPI == 0) {
        float qv[8];
        #pragma unroll
        for (int j = 0; j < 8; ++j) qv[j] = qw[b * M_ + gc + j];
        float b0 = biasp[0];
        float* O = Og + (long)b * sOb;
        #pragma unroll
        for (int i = 0; i < 8; ++i) {
            float ci = cw[b * N_ + gr + i] + b0;
            float4 o0 = make_float4(acc[i][0] + ci + qv[0], acc[i][1] + ci + qv[1],
                                    acc[i][2] + ci + qv[2], acc[i][3] + ci + qv[3]);
            float4 o1 = make_float4(acc[i][4] + ci + qv[4], acc[i][5] + ci + qv[5],
                                    acc[i][6] + ci + qv[6], acc[i][7] + ci + qv[7]);
            *(float4*)(O + (long)(gr + i) * ldo + gc)     = o0;
            *(float4*)(O + (long)(gr + i) * ldo + gc + 4) = o1;
        }
    } else if (EPI == 1) {
        float* O = Og + (long)b * sOb;
        #pragma unroll
        for (int i = 0; i < 8; ++i) {
            *(float4*)(O + (long)(gr + i) * ldo + gc) =
                make_float4(acc[i][0], acc[i][1], acc[i][2], acc[i][3]);
            *(float4*)(O + (long)(gr + i) * ldo + gc + 4) =
                make_float4(acc[i][4], acc[i][5], acc[i][6], acc[i][7]);
        }
    } else {
        const float* Cb = Cin + (long)b * N_ * D_;
        float* O = Og + (long)b * N_ * 2048;
        #pragma unroll
        for (int i = 0; i < 8; ++i) {
            const float* crow = Cb + (long)(gr + i) * D_ + gc;
            float*       orow = O  + (long)(gr + i) * 2048;
            float4 c0 = *(const float4*)(crow);
            float4 c1 = *(const float4*)(crow + 4);
            if (EPI == 2) {
                float4 a0 = make_float4(acc[i][0], acc[i][1], acc[i][2], acc[i][3]);
                float4 a1 = make_float4(acc[i][4], acc[i][5], acc[i][6], acc[i][7]);
                *(float4*)(orow + gc)            = c0;
                *(float4*)(orow + gc + 4)        = c1;
                *(float4*)(orow + 512 + gc)      = a0;
                *(float4*)(orow + 512 + gc + 4)  = a1;
                *(float4*)(orow + 1024 + gc)     =
                    make_float4(c0.x * a0.x, c0.y * a0.y, c0.z * a0.z, c0.w * a0.w);
                *(float4*)(orow + 1024 + gc + 4) =
                    make_float4(c1.x * a1.x, c1.y * a1.y, c1.z * a1.z, c1.w * a1.w);
            } else { // EPI == 3
                *(float4*)(orow + 1536 + gc) =
                    make_float4(c0.x * acc[i][0], c0.y * acc[i][1],
                                c0.z * acc[i][2], c0.w * acc[i][3]);
                *(float4*)(orow + 1536 + gc + 4) =
                    make_float4(c1.x * acc[i][4], c1.y * acc[i][5],
                                c1.z * acc[i][6], c1.w * acc[i][7]);
            }
        }
    }
}

// ---------------------------------------------------------------------------
// kernel_launch
// inputs: C[B,N,D], Q[B,M,D], Cmask[B,N], Qmask[B,M], w4C[D], w4Q[D],
//         w4mlu[D], bias[1]; out: [B,N,4D] fp32
// ---------------------------------------------------------------------------
extern "C" void kernel_launch(void* const* d_in, const int* in_sizes, int n_in,
                              void* d_out, int out_size)
{
    const float* C     = (const float*)d_in[0];
    const float* Q     = (const float*)d_in[1];
    const float* Cmask = (const float*)d_in[2];
    const float* Qmask = (const float*)d_in[3];
    const float* w4C   = (const float*)d_in[4];
    const float* w4Q   = (const float*)d_in[5];
    const float* w4mlu = (const float*)d_in[6];
    const float* bias  = (const float*)d_in[7];
    float* out = (float*)d_out;

    float *sim, *S2, *Bt, *cw, *qw;
    cudaGetSymbolAddress((void**)&sim, g_sim);
    cudaGetSymbolAddress((void**)&S2,  g_S2);
    cudaGetSymbolAddress((void**)&Bt,  g_Bt);
    cudaGetSymbolAddress((void**)&cw,  g_cw);
    cudaGetSymbolAddress((void**)&qw,  g_qw);

    // Row scalars
    rowdot_kernel<<<(B_ * N_) / 8, 256>>>(C, w4C, cw, B_ * N_);
    rowdot_kernel<<<(B_ * M_) / 8, 256>>>(Q, w4Q, qw, B_ * M_);

    // G1: sim[b,n,m] = sum_d (C*w4mlu)[n,d] * Q[m,d]  + cw + qw + bias
    dim3 g1(M_ / 128, N_ / 128, B_);
    sgemm_kernel<0, true, true><<<g1, 256>>>(
        C, (long)N_ * D_, D_,
        Q, (long)M_ * D_, D_,
        sim, (long)N_ * M_, M_,
        D_, w4mlu, cw, qw, bias, nullptr);

    // Dual softmax -> S1 (in-place sim), S2
    softmax2_kernel<<<B_ * N_, 128>>>(Qmask, Cmask);

    // G2: A = S1 @ Q  -> epilogue writes out[:,0:512]=C, [512:1024]=A, [1024:1536]=C*A
    dim3 g2(D_ / 128, N_ / 128, B_);
    sgemm_kernel<2, false, false><<<g2, 256>>>(
        sim, (long)N_ * M_, M_,
        Q, (long)M_ * D_, D_,
        out, 0, 0,
        M_, nullptr, nullptr, nullptr, nullptr, C);

    // G3: Bt = S1 @ S2^T  [B,N,N]
    dim3 g3(N_ / 128, N_ / 128, B_);
    sgemm_kernel<1, true, false><<<g3, 256>>>(
        sim, (long)N_ * M_, M_,
        S2, (long)N_ * M_, M_,
        Bt, (long)N_ * N_, N_,
        M_, nullptr, nullptr, nullptr, nullptr, nullptr);

    // G4: Bv = Bt @ C  -> epilogue writes out[:,1536:2048] = C*Bv
    dim3 g4(D_ / 128, N_ / 128, B_);
    sgemm_kernel<3, false, false><<<g4, 256>>>(
        Bt, (long)N_ * N_, N_,
        C, (long)N_ * D_, D_,
        out, 0, 0,
        N_, nullptr, nullptr, nullptr, nullptr, C);
}

// round 6
// speedup vs baseline: 1.0235x; 1.0235x over previous
#include <cuda_runtime.h>
#include <math_constants.h>
#include <cstdint>

// Problem constants: B=16, N=1024, M=512, D=512
#define B_ 16
#define N_ 1024
#define M_ 512
#define D_ 512

// Scratch (device globals; no allocation allowed)
__device__ float g_sim[B_ * N_ * M_];   // similarity, then S1 in-place (32 MB)
__device__ float g_S2 [B_ * N_ * M_];   // S2 (32 MB)
__device__ float g_Bt [B_ * N_ * N_];   // S1 @ S2^T (64 MB)
__device__ float g_cw [B_ * N_];        // C @ w4C
__device__ float g_qw [B_ * M_];        // Q @ w4Q

// ---------------------------------------------------------------------------
// Packed f32x2 helpers (Blackwell: fma.rn.f32x2 doubles fp32 FMA throughput)
// ---------------------------------------------------------------------------
__device__ __forceinline__ unsigned long long pack_dup(float a) {
    unsigned long long r;
    unsigned au = __float_as_uint(a);
    asm("mov.b64 %0, {%1, %1};" : "=l"(r) : "r"(au));
    return r;
}
__device__ __forceinline__ void fma2(unsigned long long& acc,
                                     unsigned long long a, unsigned long long b) {
    asm("fma.rn.f32x2 %0, %1, %2, %0;" : "+l"(acc) : "l"(a), "l"(b));
}
__device__ __forceinline__ float2 unpack2(unsigned long long v) {
    float lo, hi;
    asm("mov.b64 {%0, %1}, %2;" : "=f"(lo), "=f"(hi) : "l"(v));
    return make_float2(lo, hi);
}

// ---------------------------------------------------------------------------
// Row-dot: out[row] = sum_d X[row,d] * w[d], D_=512, one warp per row
// ---------------------------------------------------------------------------
__global__ __launch_bounds__(256)
void rowdot_kernel(const float* __restrict__ X, const float* __restrict__ w,
                   float* __restrict__ out, int rows)
{
    int warp = (blockIdx.x * blockDim.x + threadIdx.x) >> 5;
    int lane = threadIdx.x & 31;
    if (warp >= rows) return;
    const float4* x4 = (const float4*)(X + (long)warp * D_);
    const float4* w4 = (const float4*)w;
    float s = 0.f;
    #pragma unroll
    for (int i = 0; i < 4; ++i) {
        float4 a = x4[lane + 32 * i];
        float4 b = w4[lane + 32 * i];
        s += a.x * b.x + a.y * b.y + a.z * b.z + a.w * b.w;
    }
    #pragma unroll
    for (int o = 16; o; o >>= 1) s += __shfl_xor_sync(0xffffffffu, s, o);
    if (lane == 0) out[warp] = s;
}

// ---------------------------------------------------------------------------
// Dual softmax over M=512 per row of g_sim.
//   S1: mask Qmask over columns, write back into g_sim
//   S2: mask Cmask per-row scalar (row masked -> NaN, matches reference), g_S2
// ---------------------------------------------------------------------------
__global__ __launch_bounds__(128)
void softmax2_kernel(const float* __restrict__ Qmask, const float* __restrict__ Cmask)
{
    int row = blockIdx.x;            // b*N + n
    int b   = row >> 10;             // N_=1024
    int t   = threadIdx.x;
    int w   = t >> 5, lane = t & 31;

    float4 v  = ((const float4*)(g_sim + (long)row * M_))[t];
    float4 qm = ((const float4*)(Qmask + (long)b * M_))[t];
    float xv[4] = {v.x, v.y, v.z, v.w};
    float qv[4] = {qm.x, qm.y, qm.z, qm.w};

    float m1 = -CUDART_INF_F, m2 = -CUDART_INF_F;
    #pragma unroll
    for (int j = 0; j < 4; ++j) {
        m2 = fmaxf(m2, xv[j]);
        if (qv[j] != 0.f) m1 = fmaxf(m1, xv[j]);
    }
    #pragma unroll
    for (int o = 16; o; o >>= 1) {
        m1 = fmaxf(m1, __shfl_xor_sync(0xffffffffu, m1, o));
        m2 = fmaxf(m2, __shfl_xor_sync(0xffffffffu, m2, o));
    }
    __shared__ float sh1[4], sh2[4];
    if (lane == 0) { sh1[w] = m1; sh2[w] = m2; }
    __syncthreads();
    m1 = fmaxf(fmaxf(sh1[0], sh1[1]), fmaxf(sh1[2], sh1[3]));
    m2 = fmaxf(fmaxf(sh2[0], sh2[1]), fmaxf(sh2[2], sh2[3]));

    float e1[4], e2[4], s1 = 0.f, s2 = 0.f;
    #pragma unroll
    for (int j = 0; j < 4; ++j) {
        e2[j] = __expf(xv[j] - m2);                         s2 += e2[j];
        e1[j] = (qv[j] != 0.f) ? __expf(xv[j] - m1) : 0.f;  s1 += e1[j];
    }
    #pragma unroll
    for (int o = 16; o; o >>= 1) {
        s1 += __shfl_xor_sync(0xffffffffu, s1, o);
        s2 += __shfl_xor_sync(0xffffffffu, s2, o);
    }
    __syncthreads();
    if (lane == 0) { sh1[w] = s1; sh2[w] = s2; }
    __syncthreads();
    s1 = sh1[0] + sh1[1] + sh1[2] + sh1[3];
    s2 = sh2[0] + sh2[1] + sh2[2] + sh2[3];

    float r1 = 1.f / s1;
    float cm = Cmask[row];
    float r2 = (cm != 0.f) ? (1.f / s2) : __int_as_float(0x7FC00000);

    ((float4*)(g_sim + (long)row * M_))[t] =
        make_float4(e1[0] * r1, e1[1] * r1, e1[2] * r1, e1[3] * r1);
    ((float4*)(g_S2 + (long)row * M_))[t] =
        make_float4(e2[0] * r2, e2[1] * r2, e2[2] * r2, e2[3] * r2);
}

// ---------------------------------------------------------------------------
// Register-blocked SGEMM with packed f32x2 FMAs.
// 128x128 tile, BK=16, 256 threads, 8x8 per thread (4 packed j-pairs).
// A row-major [rows,K] (lda). B: if BT, B[col,k]; else B[k,col].
// EPI: 0 = similarity (+cw+qw+bias -> Og)
//      1 = plain store -> Og
//      2 = A-epilogue: out[.,0:512]=C, out[.,512:1024]=acc, out[.,1024:1536]=C*acc
//      3 = Bv-epilogue: out[.,1536:2048]=C*acc
// ---------------------------------------------------------------------------
template<int EPI, bool BT, bool SCALEA>
__global__ __launch_bounds__(256, 2)
void sgemm_kernel(const float* __restrict__ Ag, long sAb, int lda,
                  const float* __restrict__ Bg, long sBb, int ldb,
                  float* __restrict__ Og, long sOb, int ldo,
                  int K,
                  const float* __restrict__ wscale,
                  const float* __restrict__ cw,
                  const float* __restrict__ qw,
                  const float* __restrict__ biasp,
                  const float* __restrict__ Cin)
{
    const int b       = blockIdx.z;
    const int rowBase = blockIdx.y * 128;
    const int colBase = blockIdx.x * 128;
    const float* A  = Ag + (long)b * sAb;
    const float* Bp = Bg + (long)b * sBb;

    __shared__ float As[16][132];
    __shared__ float Bs[16][132];

    const int tid = threadIdx.x;
    const int tx  = tid & 15;
    const int ty  = tid >> 4;

    // acc[i][jp] holds columns (2jp, 2jp+1) of output row i (packed f32x2)
    unsigned long long acc[8][4];
    #pragma unroll
    for (int i = 0; i < 8; ++i)
        #pragma unroll
        for (int j = 0; j < 4; ++j) acc[i][j] = 0ull;

    for (int k0 = 0; k0 < K; k0 += 16) {
        // ---- load A tile (128 rows x 16 k), store transposed As[k][row]
        #pragma unroll
        for (int it = 0; it < 2; ++it) {
            int v  = tid + it * 256;
            int r  = v >> 2;
            int kq = (v & 3) << 2;
            float4 a = *(const float4*)(A + (long)(rowBase + r) * lda + k0 + kq);
            if (SCALEA) {
                a.x *= wscale[k0 + kq + 0]; a.y *= wscale[k0 + kq + 1];
                a.z *= wscale[k0 + kq + 2]; a.w *= wscale[k0 + kq + 3];
            }
            As[kq + 0][r] = a.x; As[kq + 1][r] = a.y;
            As[kq + 2][r] = a.z; As[kq + 3][r] = a.w;
        }
        // ---- load B tile -> Bs[k][col]
        if (BT) {
            #pragma unroll
            for (int it = 0; it < 2; ++it) {
                int v  = tid + it * 256;
                int c  = v >> 2;
                int kq = (v & 3) << 2;
                float4 bb = *(const float4*)(Bp + (long)(colBase + c) * ldb + k0 + kq);
                Bs[kq + 0][c] = bb.x; Bs[kq + 1][c] = bb.y;
                Bs[kq + 2][c] = bb.z; Bs[kq + 3][c] = bb.w;
            }
        } else {
            #pragma unroll
            for (int it = 0; it < 2; ++it) {
                int v  = tid + it * 256;
                int k  = v >> 5;
                int c4 = (v & 31) << 2;
                float4 bb = *(const float4*)(Bp + (long)(k0 + k) * ldb + colBase + c4);
                *(float4*)&Bs[k][c4] = bb;
            }
        }
        __syncthreads();

        #pragma unroll
        for (int k = 0; k < 16; ++k) {
            float ar[8];
            *(float4*)(ar)     = *(const float4*)&As[k][ty * 8];
            *(float4*)(ar + 4) = *(const float4*)&As[k][ty * 8 + 4];
            // B pairs: 64-bit aligned (tx*8 floats = 32B aligned)
            unsigned long long b2[4];
            const unsigned long long* bp =
                (const unsigned long long*)&Bs[k][tx * 8];
            b2[0] = bp[0]; b2[1] = bp[1]; b2[2] = bp[2]; b2[3] = bp[3];
            unsigned long long a2[8];
            #pragma unroll
            for (int i = 0; i < 8; ++i) a2[i] = pack_dup(ar[i]);
            #pragma unroll
            for (int i = 0; i < 8; ++i)
                #pragma unroll
                for (int j = 0; j < 4; ++j)
                    fma2(acc[i][j], a2[i], b2[j]);
        }
        __syncthreads();
    }

    const int gr = rowBase + ty * 8;
    const int gc = colBase + tx * 8;

    // unpack accumulators to scalar view per row on the fly
    if (EPI == 0) {
        float qv[8];
        #pragma unroll
        for (int j = 0; j < 8; ++j) qv[j] = qw[b * M_ + gc + j];
        float b0 = biasp[0];
        float* O = Og + (long)b * sOb;
        #pragma unroll
        for (int i = 0; i < 8; ++i) {
            float ci = cw[b * N_ + gr + i] + b0;
            float2 p0 = unpack2(acc[i][0]);
            float2 p1 = unpack2(acc[i][1]);
            float2 p2 = unpack2(acc[i][2]);
            float2 p3 = unpack2(acc[i][3]);
            float4 o0 = make_float4(p0.x + ci + qv[0], p0.y + ci + qv[1],
                                    p1.x + ci + qv[2], p1.y + ci + qv[3]);
            float4 o1 = make_float4(p2.x + ci + qv[4], p2.y + ci + qv[5],
                                    p3.x + ci + qv[6], p3.y + ci + qv[7]);
            *(float4*)(O + (long)(gr + i) * ldo + gc)     = o0;
            *(float4*)(O + (long)(gr + i) * ldo + gc + 4) = o1;
        }
    } else if (EPI == 1) {
        float* O = Og + (long)b * sOb;
        #pragma unroll
        for (int i = 0; i < 8; ++i) {
            float2 p0 = unpack2(acc[i][0]);
            float2 p1 = unpack2(acc[i][1]);
            float2 p2 = unpack2(acc[i][2]);
            float2 p3 = unpack2(acc[i][3]);
            *(float4*)(O + (long)(gr + i) * ldo + gc) =
                make_float4(p0.x, p0.y, p1.x, p1.y);
            *(float4*)(O + (long)(gr + i) * ldo + gc + 4) =
                make_float4(p2.x, p2.y, p3.x, p3.y);
        }
    } else {
        const float* Cb = Cin + (long)b * N_ * D_;
        float* O = Og + (long)b * N_ * 2048;
        #pragma unroll
        for (int i = 0; i < 8; ++i) {
            const float* crow = Cb + (long)(gr + i) * D_ + gc;
            float*       orow = O  + (long)(gr + i) * 2048;
            float4 c0 = *(const float4*)(crow);
            float4 c1 = *(const float4*)(crow + 4);
            float2 p0 = unpack2(acc[i][0]);
            float2 p1 = unpack2(acc[i][1]);
            float2 p2 = unpack2(acc[i][2]);
            float2 p3 = unpack2(acc[i][3]);
            float4 a0 = make_float4(p0.x, p0.y, p1.x, p1.y);
            float4 a1 = make_float4(p2.x, p2.y, p3.x, p3.y);
            if (EPI == 2) {
                *(float4*)(orow + gc)            = c0;
                *(float4*)(orow + gc + 4)        = c1;
                *(float4*)(orow + 512 + gc)      = a0;
                *(float4*)(orow + 512 + gc + 4)  = a1;
                *(float4*)(orow + 1024 + gc)     =
                    make_float4(c0.x * a0.x, c0.y * a0.y, c0.z * a0.z, c0.w * a0.w);
                *(float4*)(orow + 1024 + gc + 4) =
                    make_float4(c1.x * a1.x, c1.y * a1.y, c1.z * a1.z, c1.w * a1.w);
            } else { // EPI == 3
                *(float4*)(orow + 1536 + gc) =
                    make_float4(c0.x * a0.x, c0.y * a0.y, c0.z * a0.z, c0.w * a0.w);
                *(float4*)(orow + 1536 + gc + 4) =
                    make_float4(c1.x * a1.x, c1.y * a1.y, c1.z * a1.z, c1.w * a1.w);
            }
        }
    }
}

// ---------------------------------------------------------------------------
// kernel_launch
// inputs: C[B,N,D], Q[B,M,D], Cmask[B,N], Qmask[B,M], w4C[D], w4Q[D],
//         w4mlu[D], bias[1]; out: [B,N,4D] fp32
// ---------------------------------------------------------------------------
extern "C" void kernel_launch(void* const* d_in, const int* in_sizes, int n_in,
                              void* d_out, int out_size)
{
    (void)in_sizes; (void)n_in; (void)out_size;
    const float* C     = (const float*)d_in[0];
    const float* Q     = (const float*)d_in[1];
    const float* Cmask = (const float*)d_in[2];
    const float* Qmask = (const float*)d_in[3];
    const float* w4C   = (const float*)d_in[4];
    const float* w4Q   = (const float*)d_in[5];
    const float* w4mlu = (const float*)d_in[6];
    const float* bias  = (const float*)d_in[7];
    float* out = (float*)d_out;

    float *sim, *S2, *Bt, *cw, *qw;
    cudaGetSymbolAddress((void**)&sim, g_sim);
    cudaGetSymbolAddress((void**)&S2,  g_S2);
    cudaGetSymbolAddress((void**)&Bt,  g_Bt);
    cudaGetSymbolAddress((void**)&cw,  g_cw);
    cudaGetSymbolAddress((void**)&qw,  g_qw);

    // Row scalars
    rowdot_kernel<<<(B_ * N_) / 8, 256>>>(C, w4C, cw, B_ * N_);
    rowdot_kernel<<<(B_ * M_) / 8, 256>>>(Q, w4Q, qw, B_ * M_);

    // G1: sim[b,n,m] = sum_d (C*w4mlu)[n,d] * Q[m,d]  + cw + qw + bias
    dim3 g1(M_ / 128, N_ / 128, B_);
    sgemm_kernel<0, true, true><<<g1, 256>>>(
        C, (long)N_ * D_, D_,
        Q, (long)M_ * D_, D_,
        sim, (long)N_ * M_, M_,
        D_, w4mlu, cw, qw, bias, nullptr);

    // Dual softmax -> S1 (in-place sim), S2
    softmax2_kernel<<<B_ * N_, 128>>>(Qmask, Cmask);

    // G2: A = S1 @ Q  -> epilogue writes out[:,0:512]=C, [512:1024]=A, [1024:1536]=C*A
    dim3 g2(D_ / 128, N_ / 128, B_);
    sgemm_kernel<2, false, false><<<g2, 256>>>(
        sim, (long)N_ * M_, M_,
        Q, (long)M_ * D_, D_,
        out, 0, 0,
        M_, nullptr, nullptr, nullptr, nullptr, C);

    // G3: Bt = S1 @ S2^T  [B,N,N]
    dim3 g3(N_ / 128, N_ / 128, B_);
    sgemm_kernel<1, true, false><<<g3, 256>>>(
        sim, (long)N_ * M_, M_,
        S2, (long)N_ * M_, M_,
        Bt, (long)N_ * N_, N_,
        M_, nullptr, nullptr, nullptr, nullptr, nullptr);

    // G4: Bv = Bt @ C  -> epilogue writes out[:,1536:2048] = C*Bv
    dim3 g4(D_ / 128, N_ / 128, B_);
    sgemm_kernel<3, false, false><<<g4, 256>>>(
        Bt, (long)N_ * N_, N_,
        C, (long)N_ * D_, D_,
        out, 0, 0,
        N_, nullptr, nullptr, nullptr, nullptr, C);
}

// round 7
// speedup vs baseline: 2.1362x; 2.0872x over previous
#include <cuda_runtime.h>
#include <cuda_bf16.h>
#include <math_constants.h>
#include <cstdint>

// Problem constants: B=16, N=1024, M=512, D=512
#define B_ 16
#define N_ 1024
#define M_ 512
#define D_ 512

// ---------------------------------------------------------------------------
// Scratch (device globals; no allocation allowed)
// ---------------------------------------------------------------------------
__device__ float g_sim[B_ * N_ * M_];                 // similarity fp32 (32 MB)
__device__ float g_cw [B_ * N_];
__device__ float g_qw [B_ * M_];
__device__ __nv_bfloat16 g_CWh[B_ * N_ * D_];         // (C*w4mlu) hi/lo
__device__ __nv_bfloat16 g_CWl[B_ * N_ * D_];
__device__ __nv_bfloat16 g_Qh [B_ * M_ * D_];         // Q hi/lo  [m][d]
__device__ __nv_bfloat16 g_Ql [B_ * M_ * D_];
__device__ __nv_bfloat16 g_Qth[B_ * D_ * M_];         // Q^T hi/lo [d][m]
__device__ __nv_bfloat16 g_Qtl[B_ * D_ * M_];
__device__ __nv_bfloat16 g_Cth[B_ * D_ * N_];         // C^T hi/lo [d][n]
__device__ __nv_bfloat16 g_Ctl[B_ * D_ * N_];
__device__ __nv_bfloat16 g_S1h[B_ * N_ * M_];
__device__ __nv_bfloat16 g_S1l[B_ * N_ * M_];
__device__ __nv_bfloat16 g_S2h[B_ * N_ * M_];
__device__ __nv_bfloat16 g_S2l[B_ * N_ * M_];
__device__ __nv_bfloat16 g_Bth[B_ * N_ * N_];
__device__ __nv_bfloat16 g_Btl[B_ * N_ * N_];

// ---------------------------------------------------------------------------
// Helpers
// ---------------------------------------------------------------------------
__device__ __forceinline__ uint32_t smem_u32(const void* p) {
    uint32_t a;
    asm("{ .reg .u64 tmp; cvta.to.shared.u64 tmp, %1; cvt.u32.u64 %0, tmp; }"
        : "=r"(a) : "l"(p));
    return a;
}

__device__ __forceinline__ void cp16(void* dst, const void* src) {
    uint32_t d = smem_u32(dst);
    asm volatile("cp.async.ca.shared.global [%0], [%1], 16;"
                 :: "r"(d), "l"(src) : "memory");
}
#define CP_COMMIT() asm volatile("cp.async.commit_group;" ::: "memory")
#define CP_WAIT1()  asm volatile("cp.async.wait_group 1;" ::: "memory")
#define CP_WAIT0()  asm volatile("cp.async.wait_group 0;" ::: "memory")

__device__ __forceinline__ void mma16816(float* d, const unsigned* a, const unsigned* b) {
    asm volatile(
        "mma.sync.aligned.m16n8k16.row.col.f32.bf16.bf16.f32 "
        "{%0,%1,%2,%3}, {%4,%5,%6,%7}, {%8,%9}, {%0,%1,%2,%3};"
        : "+f"(d[0]), "+f"(d[1]), "+f"(d[2]), "+f"(d[3])
        : "r"(a[0]), "r"(a[1]), "r"(a[2]), "r"(a[3]), "r"(b[0]), "r"(b[1]));
}

// bf16 hi/lo split of a pair of floats
__device__ __forceinline__ __nv_bfloat162 split2(float f0, float f1, __nv_bfloat162& lo) {
    __nv_bfloat162 hi = __floats2bfloat162_rn(f0, f1);
    lo = __floats2bfloat162_rn(f0 - __low2float(hi), f1 - __high2float(hi));
    return hi;
}
__device__ __forceinline__ unsigned bf2u(__nv_bfloat162 v) {
    return *reinterpret_cast<unsigned*>(&v);
}

// ---------------------------------------------------------------------------
// Row-dot: out[row] = sum_d X[row,d] * w[d]
// ---------------------------------------------------------------------------
__global__ __launch_bounds__(256)
void rowdot_kernel(const float* __restrict__ X, const float* __restrict__ w,
                   float* __restrict__ out, int rows)
{
    int warp = (blockIdx.x * blockDim.x + threadIdx.x) >> 5;
    int lane = threadIdx.x & 31;
    if (warp >= rows) return;
    const float4* x4 = (const float4*)(X + (long)warp * D_);
    const float4* w4 = (const float4*)w;
    float s = 0.f;
    #pragma unroll
    for (int i = 0; i < 4; ++i) {
        float4 a = x4[lane + 32 * i];
        float4 b = w4[lane + 32 * i];
        s += a.x * b.x + a.y * b.y + a.z * b.z + a.w * b.w;
    }
    #pragma unroll
    for (int o = 16; o; o >>= 1) s += __shfl_xor_sync(0xffffffffu, s, o);
    if (lane == 0) out[warp] = s;
}

// ---------------------------------------------------------------------------
// Elementwise split fp32 -> bf16 hi/lo (optional per-d scale by ws)
// ---------------------------------------------------------------------------
template<bool SC>
__global__ __launch_bounds__(256)
void split_kernel(const float* __restrict__ X, const float* __restrict__ ws,
                  __nv_bfloat16* __restrict__ H, __nv_bfloat16* __restrict__ L, int n4)
{
    int i = blockIdx.x * blockDim.x + threadIdx.x;
    if (i >= n4) return;
    float4 v = ((const float4*)X)[i];
    if (SC) {
        int d = (i * 4) & (D_ - 1);
        float4 w = *(const float4*)(ws + d);
        v.x *= w.x; v.y *= w.y; v.z *= w.z; v.w *= w.w;
    }
    __nv_bfloat162 l0, l1;
    __nv_bfloat162 h0 = split2(v.x, v.y, l0);
    __nv_bfloat162 h1 = split2(v.z, v.w, l1);
    ((uint2*)H)[i] = make_uint2(bf2u(h0), bf2u(h1));
    ((uint2*)L)[i] = make_uint2(bf2u(l0), bf2u(l1));
}

// ---------------------------------------------------------------------------
// Transpose + split: X[b][R][Cc] fp32 -> Th/Tl[b][Cc][R] bf16
// ---------------------------------------------------------------------------
__global__ __launch_bounds__(256)
void transpose_split_kernel(const float* __restrict__ X, int R, int Cc,
                            __nv_bfloat16* __restrict__ Th, __nv_bfloat16* __restrict__ Tl)
{
    __shared__ float tile[32][33];
    int b = blockIdx.z;
    const float* Xb = X + (long)b * R * Cc;
    __nv_bfloat16* Thb = Th + (long)b * R * Cc;
    __nv_bfloat16* Tlb = Tl + (long)b * R * Cc;
    int rb = blockIdx.y * 32, cb = blockIdx.x * 32;
    int tx = threadIdx.x & 31, ty = threadIdx.x >> 5;   // 32 x 8
    #pragma unroll
    for (int i = 0; i < 4; ++i)
        tile[ty + 8 * i][tx] = Xb[(long)(rb + ty + 8 * i) * Cc + cb + tx];
    __syncthreads();
    #pragma unroll
    for (int i = 0; i < 4; ++i) {
        float v = tile[tx][ty + 8 * i];
        long oi = (long)(cb + ty + 8 * i) * R + rb + tx;
        __nv_bfloat16 h = __float2bfloat16(v);
        Thb[oi] = h;
        Tlb[oi] = __float2bfloat16(v - __bfloat162float(h));
    }
}

// ---------------------------------------------------------------------------
// Dual softmax over M=512 per row; writes bf16 hi/lo splits of S1 and S2.
// ---------------------------------------------------------------------------
__global__ __launch_bounds__(128)
void softmax2_kernel(const float* __restrict__ Qmask, const float* __restrict__ Cmask)
{
    int row = blockIdx.x;            // b*N + n
    int b   = row >> 10;
    int t   = threadIdx.x;
    int w   = t >> 5, lane = t & 31;

    float4 v  = ((const float4*)(g_sim + (long)row * M_))[t];
    float4 qm = ((const float4*)(Qmask + (long)b * M_))[t];
    float xv[4] = {v.x, v.y, v.z, v.w};
    float qv[4] = {qm.x, qm.y, qm.z, qm.w};

    float m1 = -CUDART_INF_F, m2 = -CUDART_INF_F;
    #pragma unroll
    for (int j = 0; j < 4; ++j) {
        m2 = fmaxf(m2, xv[j]);
        if (qv[j] != 0.f) m1 = fmaxf(m1, xv[j]);
    }
    #pragma unroll
    for (int o = 16; o; o >>= 1) {
        m1 = fmaxf(m1, __shfl_xor_sync(0xffffffffu, m1, o));
        m2 = fmaxf(m2, __shfl_xor_sync(0xffffffffu, m2, o));
    }
    __shared__ float sh1[4], sh2[4];
    if (lane == 0) { sh1[w] = m1; sh2[w] = m2; }
    __syncthreads();
    m1 = fmaxf(fmaxf(sh1[0], sh1[1]), fmaxf(sh1[2], sh1[3]));
    m2 = fmaxf(fmaxf(sh2[0], sh2[1]), fmaxf(sh2[2], sh2[3]));

    float e1[4], e2[4], s1 = 0.f, s2 = 0.f;
    #pragma unroll
    for (int j = 0; j < 4; ++j) {
        e2[j] = __expf(xv[j] - m2);                         s2 += e2[j];
        e1[j] = (qv[j] != 0.f) ? __expf(xv[j] - m1) : 0.f;  s1 += e1[j];
    }
    #pragma unroll
    for (int o = 16; o; o >>= 1) {
        s1 += __shfl_xor_sync(0xffffffffu, s1, o);
        s2 += __shfl_xor_sync(0xffffffffu, s2, o);
    }
    __syncthreads();
    if (lane == 0) { sh1[w] = s1; sh2[w] = s2; }
    __syncthreads();
    s1 = sh1[0] + sh1[1] + sh1[2] + sh1[3];
    s2 = sh2[0] + sh2[1] + sh2[2] + sh2[3];

    float r1 = 1.f / s1;
    float cm = Cmask[row];
    float r2 = (cm != 0.f) ? (1.f / s2) : __int_as_float(0x7FC00000);

    long o8 = (long)row * (M_ / 4) + t;   // uint2 index (4 bf16 per thread)
    {
        __nv_bfloat162 l0, l1;
        __nv_bfloat162 h0 = split2(e1[0] * r1, e1[1] * r1, l0);
        __nv_bfloat162 h1 = split2(e1[2] * r1, e1[3] * r1, l1);
        ((uint2*)g_S1h)[o8] = make_uint2(bf2u(h0), bf2u(h1));
        ((uint2*)g_S1l)[o8] = make_uint2(bf2u(l0), bf2u(l1));
    }
    {
        __nv_bfloat162 l0, l1;
        __nv_bfloat162 h0 = split2(e2[0] * r2, e2[1] * r2, l0);
        __nv_bfloat162 h1 = split2(e2[2] * r2, e2[3] * r2, l1);
        ((uint2*)g_S2h)[o8] = make_uint2(bf2u(h0), bf2u(h1));
        ((uint2*)g_S2l)[o8] = make_uint2(bf2u(l0), bf2u(l1));
    }
}

// ---------------------------------------------------------------------------
// mma.sync bf16 hi/lo-split GEMM.
//   D[r,c] = sum_k A[r,k]*B[c,k], A = Ah+Al, B = Bh+Bl (3 MMA products).
// CTA: 128x128, 8 warps (2 M x 4 N), warp tile 64x32, BK=32, cp.async 2-stage.
// SMEM per stage (bf16 elems, k-stride 40): Ah@0, Al@5120, Bh@10240, Bl@15360.
// EPI: 0 = similarity (+cw[row]+qw[col]+bias -> simO fp32)
//      1 = Bt-epilogue (split acc -> BtH/BtL bf16)
//      2 = A-epilogue  (out[.,0:512]=C, [512:1024]=acc, [1024:1536]=C*acc)
//      3 = Bv-epilogue (out[.,1536:2048]=C*acc)
// ---------------------------------------------------------------------------
#define STAGE_ELEMS 20480
#define SMEM_BYTES  (2 * STAGE_ELEMS * 2)   // 81920

__device__ __forceinline__ void stage_load(__nv_bfloat16* sm, int buf,
    const __nv_bfloat16* __restrict__ Ahp, const __nv_bfloat16* __restrict__ Alp,
    const __nv_bfloat16* __restrict__ Bhp, const __nv_bfloat16* __restrict__ Blp,
    int lda, int ldb, int k0, int tid)
{
    #pragma unroll
    for (int it = 0; it < 2; ++it) {
        int v = tid + (it << 8);
        int r = v >> 2, j = v & 3;
        long aoff = (long)r * lda + k0 + j * 8;
        long boff = (long)r * ldb + k0 + j * 8;
        int  doff = buf * STAGE_ELEMS + r * 40 + j * 8;
        cp16(sm + doff,          Ahp + aoff);
        cp16(sm + doff + 5120,   Alp + aoff);
        cp16(sm + doff + 10240,  Bhp + boff);
        cp16(sm + doff + 15360,  Blp + boff);
    }
    CP_COMMIT();
}

template<int EPI>
__global__ __launch_bounds__(256)
void mma_gemm(const __nv_bfloat16* __restrict__ Ah_, const __nv_bfloat16* __restrict__ Al_,
              long sAb, int lda,
              const __nv_bfloat16* __restrict__ Bh_, const __nv_bfloat16* __restrict__ Bl_,
              long sBb, int ldb, int K,
              float* __restrict__ simO,
              const float* __restrict__ cw, const float* __restrict__ qw,
              const float* __restrict__ biasp,
              const float* __restrict__ Cin, float* __restrict__ out,
              __nv_bfloat16* __restrict__ BtH, __nv_bfloat16* __restrict__ BtL)
{
    extern __shared__ __nv_bfloat16 sm[];
    const int tid  = threadIdx.x;
    const int w    = tid >> 5, lane = tid & 31;
    const int g    = lane >> 2, t = lane & 3;
    const int wm   = w & 1, wn = w >> 1;
    const int b    = blockIdx.z;
    const int rowBase = blockIdx.y * 128;
    const int colBase = blockIdx.x * 128;

    const __nv_bfloat16* Ahp = Ah_ + (long)b * sAb + (long)rowBase * lda;
    const __nv_bfloat16* Alp = Al_ + (long)b * sAb + (long)rowBase * lda;
    const __nv_bfloat16* Bhp = Bh_ + (long)b * sBb + (long)colBase * ldb;
    const __nv_bfloat16* Blp = Bl_ + (long)b * sBb + (long)colBase * ldb;

    float d[4][4][4];
    #pragma unroll
    for (int mi = 0; mi < 4; ++mi)
        #pragma unroll
        for (int ni = 0; ni < 4; ++ni)
            #pragma unroll
            for (int r = 0; r < 4; ++r) d[mi][ni][r] = 0.f;

    const int NCH = K >> 5;
    stage_load(sm, 0, Ahp, Alp, Bhp, Blp, lda, ldb, 0, tid);

    for (int c = 0; c < NCH; ++c) {
        if (c + 1 < NCH) {
            stage_load(sm, (c + 1) & 1, Ahp, Alp, Bhp, Blp, lda, ldb, (c + 1) << 5, tid);
            CP_WAIT1();
        } else {
            CP_WAIT0();
        }
        __syncthreads();
        const __nv_bfloat16* S = sm + (c & 1) * STAGE_ELEMS;
        #pragma unroll
        for (int ks = 0; ks < 32; ks += 16) {
            unsigned ah[4][4], al[4][4], bh[4][2], bl[4][2];
            #pragma unroll
            for (int mi = 0; mi < 4; ++mi) {
                int i0 = (wm * 64 + mi * 16 + g) * 40 + ks + t * 2;
                ah[mi][0] = *(const unsigned*)(S + i0);
                ah[mi][1] = *(const unsigned*)(S + i0 + 320);
                ah[mi][2] = *(const unsigned*)(S + i0 + 8);
                ah[mi][3] = *(const unsigned*)(S + i0 + 328);
                al[mi][0] = *(const unsigned*)(S + i0 + 5120);
                al[mi][1] = *(const unsigned*)(S + i0 + 5440);
                al[mi][2] = *(const unsigned*)(S + i0 + 5128);
                al[mi][3] = *(const unsigned*)(S + i0 + 5448);
            }
            #pragma unroll
            for (int ni = 0; ni < 4; ++ni) {
                int i0 = 10240 + (wn * 32 + ni * 8 + g) * 40 + ks + t * 2;
                bh[ni][0] = *(const unsigned*)(S + i0);
                bh[ni][1] = *(const unsigned*)(S + i0 + 8);
                bl[ni][0] = *(const unsigned*)(S + i0 + 5120);
                bl[ni][1] = *(const unsigned*)(S + i0 + 5128);
            }
            #pragma unroll
            for (int mi = 0; mi < 4; ++mi)
                #pragma unroll
                for (int ni = 0; ni < 4; ++ni) {
                    mma16816(d[mi][ni], ah[mi], bh[ni]);
                    mma16816(d[mi][ni], ah[mi], bl[ni]);
                    mma16816(d[mi][ni], al[mi], bh[ni]);
                }
        }
        __syncthreads();
    }

    // ---- epilogue: lane holds (r0,col..col+1) in d[..][0,1], (r1,..) in d[..][2,3]
    const int mrow0 = rowBase + wm * 64;
    const int ncol0 = colBase + wn * 32;

    if (EPI == 0) {
        float bb = biasp[0];
        #pragma unroll
        for (int mi = 0; mi < 4; ++mi) {
            int r0 = mrow0 + mi * 16 + g, r1 = r0 + 8;
            float c0 = cw[b * N_ + r0] + bb;
            float c1 = cw[b * N_ + r1] + bb;
            #pragma unroll
            for (int ni = 0; ni < 4; ++ni) {
                int col = ncol0 + ni * 8 + t * 2;
                float2 q = *(const float2*)(qw + b * M_ + col);
                float2 o0 = make_float2(d[mi][ni][0] + c0 + q.x, d[mi][ni][1] + c0 + q.y);
                float2 o1 = make_float2(d[mi][ni][2] + c1 + q.x, d[mi][ni][3] + c1 + q.y);
                *(float2*)(simO + ((long)b * N_ + r0) * M_ + col) = o0;
                *(float2*)(simO + ((long)b * N_ + r1) * M_ + col) = o1;
            }
        }
    } else if (EPI == 1) {
        #pragma unroll
        for (int mi = 0; mi < 4; ++mi) {
            int r0 = mrow0 + mi * 16 + g, r1 = r0 + 8;
            #pragma unroll
            for (int ni = 0; ni < 4; ++ni) {
                int col = ncol0 + ni * 8 + t * 2;
                __nv_bfloat162 lo0, lo1;
                __nv_bfloat162 hi0 = split2(d[mi][ni][0], d[mi][ni][1], lo0);
                __nv_bfloat162 hi1 = split2(d[mi][ni][2], d[mi][ni][3], lo1);
                *(unsigned*)(BtH + ((long)b * N_ + r0) * N_ + col) = bf2u(hi0);
                *(unsigned*)(BtL + ((long)b * N_ + r0) * N_ + col) = bf2u(lo0);
                *(unsigned*)(BtH + ((long)b * N_ + r1) * N_ + col) = bf2u(hi1);
                *(unsigned*)(BtL + ((long)b * N_ + r1) * N_ + col) = bf2u(lo1);
            }
        }
    } else {
        const float* Cb = Cin + (long)b * N_ * D_;
        float* Ob = out + (long)b * N_ * 2048;
        #pragma unroll
        for (int mi = 0; mi < 4; ++mi) {
            int r0 = mrow0 + mi * 16 + g, r1 = r0 + 8;
            #pragma unroll
            for (int ni = 0; ni < 4; ++ni) {
                int col = ncol0 + ni * 8 + t * 2;
                float2 cv0 = *(const float2*)(Cb + (long)r0 * D_ + col);
                float2 cv1 = *(const float2*)(Cb + (long)r1 * D_ + col);
                float2 a0 = make_float2(d[mi][ni][0], d[mi][ni][1]);
                float2 a1 = make_float2(d[mi][ni][2], d[mi][ni][3]);
                float* o0 = Ob + (long)r0 * 2048;
                float* o1 = Ob + (long)r1 * 2048;
                if (EPI == 2) {
                    *(float2*)(o0 + col)        = cv0;
                    *(float2*)(o0 + 512 + col)  = a0;
                    *(float2*)(o0 + 1024 + col) = make_float2(cv0.x * a0.x, cv0.y * a0.y);
                    *(float2*)(o1 + col)        = cv1;
                    *(float2*)(o1 + 512 + col)  = a1;
                    *(float2*)(o1 + 1024 + col) = make_float2(cv1.x * a1.x, cv1.y * a1.y);
                } else { // EPI == 3
                    *(float2*)(o0 + 1536 + col) = make_float2(cv0.x * a0.x, cv0.y * a0.y);
                    *(float2*)(o1 + 1536 + col) = make_float2(cv1.x * a1.x, cv1.y * a1.y);
                }
            }
        }
    }
}

// ---------------------------------------------------------------------------
// kernel_launch
// inputs: C[B,N,D], Q[B,M,D], Cmask[B,N], Qmask[B,M], w4C[D], w4Q[D],
//         w4mlu[D], bias[1]; out: [B,N,4D] fp32
// ---------------------------------------------------------------------------
extern "C" void kernel_launch(void* const* d_in, const int* in_sizes, int n_in,
                              void* d_out, int out_size)
{
    (void)in_sizes; (void)n_in; (void)out_size;
    const float* C     = (const float*)d_in[0];
    const float* Q     = (const float*)d_in[1];
    const float* Cmask = (const float*)d_in[2];
    const float* Qmask = (const float*)d_in[3];
    const float* w4C   = (const float*)d_in[4];
    const float* w4Q   = (const float*)d_in[5];
    const float* w4mlu = (const float*)d_in[6];
    const float* bias  = (const float*)d_in[7];
    float* out = (float*)d_out;

    float *sim, *cw, *qw;
    __nv_bfloat16 *CWh, *CWl, *Qh, *Ql, *Qth, *Qtl, *Cth, *Ctl;
    __nv_bfloat16 *S1h, *S1l, *S2h, *S2l, *Bth, *Btl;
    cudaGetSymbolAddress((void**)&sim, g_sim);
    cudaGetSymbolAddress((void**)&cw,  g_cw);
    cudaGetSymbolAddress((void**)&qw,  g_qw);
    cudaGetSymbolAddress((void**)&CWh, g_CWh);
    cudaGetSymbolAddress((void**)&CWl, g_CWl);
    cudaGetSymbolAddress((void**)&Qh,  g_Qh);
    cudaGetSymbolAddress((void**)&Ql,  g_Ql);
    cudaGetSymbolAddress((void**)&Qth, g_Qth);
    cudaGetSymbolAddress((void**)&Qtl, g_Qtl);
    cudaGetSymbolAddress((void**)&Cth, g_Cth);
    cudaGetSymbolAddress((void**)&Ctl, g_Ctl);
    cudaGetSymbolAddress((void**)&S1h, g_S1h);
    cudaGetSymbolAddress((void**)&S1l, g_S1l);
    cudaGetSymbolAddress((void**)&S2h, g_S2h);
    cudaGetSymbolAddress((void**)&S2l, g_S2l);
    cudaGetSymbolAddress((void**)&Bth, g_Bth);
    cudaGetSymbolAddress((void**)&Btl, g_Btl);

    cudaFuncSetAttribute(mma_gemm<0>, cudaFuncAttributeMaxDynamicSharedMemorySize, SMEM_BYTES);
    cudaFuncSetAttribute(mma_gemm<1>, cudaFuncAttributeMaxDynamicSharedMemorySize, SMEM_BYTES);
    cudaFuncSetAttribute(mma_gemm<2>, cudaFuncAttributeMaxDynamicSharedMemorySize, SMEM_BYTES);
    cudaFuncSetAttribute(mma_gemm<3>, cudaFuncAttributeMaxDynamicSharedMemorySize, SMEM_BYTES);

    // 1) row scalars
    rowdot_kernel<<<(B_ * N_) / 8, 256>>>(C, w4C, cw, B_ * N_);
    rowdot_kernel<<<(B_ * M_) / 8, 256>>>(Q, w4Q, qw, B_ * M_);

    // 2) splits: CW = (C*w4mlu), Q
    {
        int n4 = B_ * N_ * D_ / 4;
        split_kernel<true><<<n4 / 256, 256>>>(C, w4mlu, CWh, CWl, n4);
    }
    {
        int n4 = B_ * M_ * D_ / 4;
        split_kernel<false><<<n4 / 256, 256>>>(Q, nullptr, Qh, Ql, n4);
    }

    // 3) transposed splits: Qt [D,M], Ct [D,N]
    {
        dim3 g(D_ / 32, M_ / 32, B_);
        transpose_split_kernel<<<g, 256>>>(Q, M_, D_, Qth, Qtl);
    }
    {
        dim3 g(D_ / 32, N_ / 32, B_);
        transpose_split_kernel<<<g, 256>>>(C, N_, D_, Cth, Ctl);
    }

    // 4) G1: sim[n,m] = sum_d CW[n,d]*Q[m,d] + cw + qw + bias
    {
        dim3 g(M_ / 128, N_ / 128, B_);
        mma_gemm<0><<<g, 256, SMEM_BYTES>>>(
            CWh, CWl, (long)N_ * D_, D_,
            Qh,  Ql,  (long)M_ * D_, D_,
            D_, sim, cw, qw, bias, nullptr, nullptr, nullptr, nullptr);
    }

    // 5) dual softmax -> S1 hi/lo, S2 hi/lo
    softmax2_kernel<<<B_ * N_, 128>>>(Qmask, Cmask);

    // 6) G2: A = S1 @ Q  (B = Qt [d][m]) -> out[:,0:1536] epilogue
    {
        dim3 g(D_ / 128, N_ / 128, B_);
        mma_gemm<2><<<g, 256, SMEM_BYTES>>>(
            S1h, S1l, (long)N_ * M_, M_,
            Qth, Qtl, (long)D_ * M_, M_,
            M_, nullptr, nullptr, nullptr, nullptr, C, out, nullptr, nullptr);
    }

    // 7) G3: Bt = S1 @ S2^T (B = S2 [n'][m]) -> split bf16 Bt
    {
        dim3 g(N_ / 128, N_ / 128, B_);
        mma_gemm<1><<<g, 256, SMEM_BYTES>>>(
            S1h, S1l, (long)N_ * M_, M_,
            S2h, S2l, (long)N_ * M_, M_,
            M_, nullptr, nullptr, nullptr, nullptr, nullptr, nullptr, Bth, Btl);
    }

    // 8) G4: Bv = Bt @ C (B = Ct [d][n']) -> out[:,1536:2048] = C*Bv
    {
        dim3 g(D_ / 128, N_ / 128, B_);
        mma_gemm<3><<<g, 256, SMEM_BYTES>>>(
            Bth, Btl, (long)N_ * N_, N_,
            Cth, Ctl, (long)D_ * N_, N_,
            N_, nullptr, nullptr, nullptr, nullptr, C, out, nullptr, nullptr);
    }
}